// round 17
// baseline (speedup 1.0000x reference)
#include <cuda_runtime.h>
#include <cuda_fp16.h>
#include <math.h>
#include <stdint.h>

#define BATCH 32768
#define FDIM 512
#define HS 256
#define OUTD 128
#define STEPS 5
#define EPSBN 1e-5f

typedef __half fp16;

// ---------------- scratch (device globals; no allocation) ----------------
__device__ fp16  g_featsh[BATCH * FDIM];
__device__ fp16  g_A[BATCH * FDIM];
__device__ fp16  g_h0[BATCH * HS];
__device__ fp16  g_h1[BATCH * HS];
__device__ float g_z[BATCH * FDIM];
__device__ float g_prior[BATCH * FDIM];
__device__ float g_acc[BATCH * OUTD];
__device__ unsigned g_cnt[BATCH / 64];

// prepped weights ([N,K] fp16; GLU ones N-permuted with 8-col a/b interleave)
__device__ fp16 g_W0[512 * 512];
__device__ fp16 g_W1[512 * 256];
__device__ fp16 g_WU[12 * 512 * 256];
__device__ fp16 g_WA[5 * 512 * 128];
__device__ float g_fts[6 * 4 * 512], g_ftt[6 * 4 * 512];
__device__ float g_as[5 * 512], g_at[5 * 512];

// ---------------- PTX helpers ----------------
__device__ __forceinline__ uint32_t smem_u32(const void* p) {
    uint32_t a;
    asm("{ .reg .u64 t; cvta.to.shared.u64 t, %1; cvt.u32.u64 %0, t; }" : "=r"(a) : "l"(p));
    return a;
}
__device__ __forceinline__ void cpa16(uint32_t s, const void* g) {
    asm volatile("cp.async.cg.shared.global [%0], [%1], 16;" :: "r"(s), "l"(g));
}
__device__ __forceinline__ void cpa_commit() {
    asm volatile("cp.async.commit_group;" ::: "memory");
}
template<int N>
__device__ __forceinline__ void cpa_wait() {
    asm volatile("cp.async.wait_group %0;" :: "n"(N) : "memory");
}
__device__ __forceinline__ void ldm4(uint32_t* v, uint32_t addr) {
    asm volatile("ldmatrix.sync.aligned.m8n8.x4.shared.b16 {%0,%1,%2,%3}, [%4];"
                 : "=r"(v[0]), "=r"(v[1]), "=r"(v[2]), "=r"(v[3]) : "r"(addr));
}
__device__ __forceinline__ void mma16(float* c, const uint32_t* a, uint32_t b0, uint32_t b1) {
    asm("mma.sync.aligned.m16n8k16.row.col.f32.f16.f16.f32 "
        "{%0,%1,%2,%3}, {%4,%5,%6,%7}, {%8,%9}, {%0,%1,%2,%3};"
        : "+f"(c[0]), "+f"(c[1]), "+f"(c[2]), "+f"(c[3])
        : "r"(a[0]), "r"(a[1]), "r"(a[2]), "r"(a[3]), "r"(b0), "r"(b1));
}

// ---------------- fused setup: init + tiled-transpose weight prep + bn ------
#define INIT2_BLK (BATCH * FDIM / 1024)     // 16384
#define T_W0 64
#define T_W1 32
#define T_WU (12 * 32)
#define T_WA (5 * 16)
#define T_TILES (T_W0 + T_W1 + T_WU + T_WA) // 560
#define BN_BLK 48
#define SETUP_BLK (INIT2_BLK + T_TILES + BN_BLK)

__global__ void k_setup(const float* __restrict__ feat,
                        const float* __restrict__ g0, const float* __restrict__ b0,
                        const float* __restrict__ m0, const float* __restrict__ v0,
                        const float* __restrict__ Ws0,
                        const float* __restrict__ Ws1,
                        const float* __restrict__ Wu,
                        const float* __restrict__ Wa,
                        const float* __restrict__ fg, const float* __restrict__ fb,
                        const float* __restrict__ fm, const float* __restrict__ fv,
                        const float* __restrict__ ag, const float* __restrict__ ab,
                        const float* __restrict__ am, const float* __restrict__ av)
{
    __shared__ float tile[64][65];
    const int b = blockIdx.x;
    const int t = threadIdx.x;

    if (b < INIT2_BLK) {
        const int base = (b * 256 + t) * 4;
        const int c = base & (FDIM - 1);
        float4 f = *(const float4*)(feat + base);
        float4 gg = *(const float4*)(g0 + c);
        float4 bb = *(const float4*)(b0 + c);
        float4 mm = *(const float4*)(m0 + c);
        float4 vv = *(const float4*)(v0 + c);
        float o0 = gg.x * (f.x - mm.x) * rsqrtf(vv.x + EPSBN) + bb.x;
        float o1 = gg.y * (f.y - mm.y) * rsqrtf(vv.y + EPSBN) + bb.y;
        float o2 = gg.z * (f.z - mm.z) * rsqrtf(vv.z + EPSBN) + bb.z;
        float o3 = gg.w * (f.w - mm.w) * rsqrtf(vv.w + EPSBN) + bb.w;
        __half2 h01, h23;
        h01.x = __float2half_rn(o0); h01.y = __float2half_rn(o1);
        h23.x = __float2half_rn(o2); h23.y = __float2half_rn(o3);
        *(__half2*)(g_featsh + base) = h01;
        *(__half2*)(g_featsh + base + 2) = h23;
        *(__half2*)(g_A + base) = h01;
        *(__half2*)(g_A + base + 2) = h23;
        if (base < BATCH * OUTD) {
            float4 z4 = {0.f, 0.f, 0.f, 0.f};
            *(float4*)(g_acc + base) = z4;
        }
        return;
    }
    if (b < INIT2_BLK + T_TILES) {
        int r = b - INIT2_BLK;
        const float* src;
        fp16* dst;
        int K, kt, nt, perm;
        if (r < T_W0) {
            src = Ws0; dst = g_W0; K = 512; perm = 1;
            kt = (r >> 3) * 64; nt = (r & 7) * 64;
        } else if (r < T_W0 + T_W1) {
            r -= T_W0;
            src = Ws1; dst = g_W1; K = 256; perm = 1;
            kt = (r >> 3) * 64; nt = (r & 7) * 64;
        } else if (r < T_W0 + T_W1 + T_WU) {
            r -= T_W0 + T_W1;
            int mi = r >> 5, rr = r & 31;
            src = Wu + (size_t)mi * 256 * 512;
            dst = g_WU + (size_t)mi * 512 * 256;
            K = 256; perm = 1;
            kt = (rr >> 3) * 64; nt = (rr & 7) * 64;
        } else {
            r -= T_W0 + T_W1 + T_WU;
            int si = r >> 4, rr = r & 15;
            src = Wa + (size_t)si * 128 * 512;
            dst = g_WA + (size_t)si * 512 * 128;
            K = 128; perm = 0;
            kt = (rr >> 3) * 64; nt = (rr & 7) * 64;
        }
        const int c0 = nt >> 1;
#pragma unroll
        for (int i = 0; i < 16; i++) {
            int lin = i * 256 + t;
            int rr2 = lin >> 6, cc = lin & 63;
            int col = perm ? ((cc < 32) ? (c0 + cc) : (256 + c0 + cc - 32)) : (nt + cc);
            tile[rr2][cc] = src[(size_t)(kt + rr2) * 512 + col];
        }
        __syncthreads();
#pragma unroll
        for (int i = 0; i < 16; i++) {
            int lin = i * 256 + t;
            int dn = lin >> 6, dk = lin & 63;
            int cc;
            if (perm) {
                int half = (dn >> 3) & 1, jl = dn & 7, qq = dn >> 4;
                cc = half * 32 + qq * 8 + jl;
            } else {
                cc = dn;
            }
            dst[(size_t)(nt + dn) * K + kt + dk] = __float2half_rn(tile[dk][cc]);
        }
        return;
    }
    {
        int idx = (b - INIT2_BLK - T_TILES) * 256 + t;
        if (idx < 6 * 4 * 512) {
            float s = fg[idx] * rsqrtf(fv[idx] + EPSBN);
            g_fts[idx] = s;
            g_ftt[idx] = fb[idx] - fm[idx] * s;
        }
        if (idx < 5 * 512) {
            float s = ag[idx] * rsqrtf(av[idx] + EPSBN);
            g_as[idx] = s;
            g_at[idx] = ab[idx] - am[idx] * s;
        }
        if (idx < BATCH / 64) g_cnt[idx] = 0u;
    }
}

// ================= small-tile GEMM: MODE 0 GLU / MODE 1 att+sparsemax =======
// 256 threads, 3 CTAs/SM. BM=64, BN=128, BK=64. Warp grid 2(M)x4(N), tile 32x32.
// MODE 1: after z epilogue, the last CTA of each 64-row block (atomic counter)
// runs sparsemax for those rows in-kernel. PR=0: first step (prior == 1).
#define STAGE_S 24576     // A 8K | B 16K
#define NSTAGE 3
#define PARAM_S (NSTAGE * STAGE_S)
#define SMEM_S  (PARAM_S + 1024)

template<int MODE, int PR>
__global__ __launch_bounds__(256, 3)
void k_mma_s(const fp16* __restrict__ A, int lda, int K,
             const fp16* __restrict__ B,
             const float* __restrict__ bs, const float* __restrict__ bt,
             const fp16* __restrict__ resh,
             fp16* __restrict__ outh,
             float* __restrict__ accp,
             float* __restrict__ prior, float* __restrict__ zout,
             float* __restrict__ maskOut, fp16* __restrict__ mf)
{
    extern __shared__ __align__(128) char smem[];
    const int tid = threadIdx.x, wid = tid >> 5, lid = tid & 31;
    const int wm = wid >> 2, wn = wid & 3;
    const int g = blockIdx.x;
    const int row0 = blockIdx.y * 64;
    const uint32_t sb = smem_u32(smem);

    if (tid < 128) {
        float* sE = (float*)(smem + PARAM_S);
        float* tE = (float*)(smem + PARAM_S + 512);
        int col;
        if (MODE == 0) {
            int q2 = tid >> 4, rr = tid & 15, half = rr >> 3, jl = rr & 7;
            col = (half ? 256 : 0) + g * 64 + q2 * 8 + jl;
        } else {
            col = g * 128 + tid;
        }
        sE[tid] = bs[col];
        tE[tid] = bt[col];
    }

    float acc[8][4];
#pragma unroll
    for (int i = 0; i < 8; i++)
#pragma unroll
        for (int j = 0; j < 4; j++) acc[i][j] = 0.0f;

    const int nch = K >> 6;

    const char* gA[2];
    const char* gB[4];
    uint32_t soA[2], soB[4];
#pragma unroll
    for (int i = 0; i < 2; i++) {
        int idx = tid + i * 256;
        int r = idx >> 3, c = idx & 7;
        soA[i] = (uint32_t)(r * 128 + ((c ^ (r & 7)) << 4));
        gA[i] = (const char*)(A + (size_t)(row0 + r) * lda + c * 8);
    }
#pragma unroll
    for (int i = 0; i < 4; i++) {
        int idx = tid + i * 256;
        int r = idx >> 3, c = idx & 7;
        soB[i] = (uint32_t)(8192 + r * 128 + ((c ^ (r & 7)) << 4));
        gB[i] = (const char*)(B + (size_t)(g * 128 + r) * K + c * 8);
    }

    auto load_stage = [&](int ch) {
        const uint32_t st = sb + (ch % NSTAGE) * STAGE_S;
        const int kb = ch << 7;
#pragma unroll
        for (int i = 0; i < 2; i++) cpa16(st + soA[i], gA[i] + kb);
#pragma unroll
        for (int i = 0; i < 4; i++) cpa16(st + soB[i], gB[i] + kb);
    };

#pragma unroll
    for (int p = 0; p < 2; p++) {
        if (p < nch) load_stage(p);
        cpa_commit();
    }

    const int lr = lid & 15, lc = lid >> 4;
    uint32_t offA[2], offB2[2];
#pragma unroll
    for (int m = 0; m < 2; m++) {
        int r = wm * 32 + m * 16 + lr;
        offA[m] = (uint32_t)(r * 128 + ((lc ^ (r & 7)) << 4));
    }
#pragma unroll
    for (int q = 0; q < 2; q++) {
        int r = wn * 32 + q * 16 + lr;
        offB2[q] = (uint32_t)(8192 + r * 128 + ((lc ^ (r & 7)) << 4));
    }

    for (int ch = 0; ch < nch; ch++) {
        cpa_wait<1>();
        __syncthreads();
        if (ch + 2 < nch) load_stage(ch + 2);
        cpa_commit();

        const uint32_t st = sb + (ch % NSTAGE) * STAGE_S;
        uint32_t aH0 = st + offA[0], aH1 = st + offA[1];
        uint32_t aB0 = st + offB2[0], aB1 = st + offB2[1];

#pragma unroll
        for (int ks = 0; ks < 4; ks++) {
            uint32_t ah[2][4], bq[2][4];
            ldm4(ah[0], aH0); ldm4(ah[1], aH1);
            ldm4(bq[0], aB0); ldm4(bq[1], aB1);
#pragma unroll
            for (int m = 0; m < 2; m++) {
                mma16(acc[m * 4 + 0], ah[m], bq[0][0], bq[0][2]);
                mma16(acc[m * 4 + 1], ah[m], bq[0][1], bq[0][3]);
                mma16(acc[m * 4 + 2], ah[m], bq[1][0], bq[1][2]);
                mma16(acc[m * 4 + 3], ah[m], bq[1][1], bq[1][3]);
            }
            const uint32_t d = (ks & 1) ? 96u : 32u;
            aH0 ^= d; aH1 ^= d;
            aB0 ^= d; aB1 ^= d;
        }
    }

    const float* sE = (const float*)(smem + PARAM_S);
    const float* tE = (const float*)(smem + PARAM_S + 512);
    const int gid = lid >> 2, tp = lid & 3;

    if (MODE == 0) {
#pragma unroll
        for (int m = 0; m < 2; m++) {
#pragma unroll
            for (int t = 0; t < 2; t++) {
                const int ja = wn * 32 + t * 16 + tp * 2;
                const int jb = ja + 8;
                const int cn = g * 64 + (wn * 2 + t) * 8 + tp * 2;
                const float sa0 = sE[ja], sa1 = sE[ja + 1];
                const float ta0 = tE[ja], ta1 = tE[ja + 1];
                const float sb0 = sE[jb], sb1 = sE[jb + 1];
                const float tb0 = tE[jb], tb1 = tE[jb + 1];
                const float* ca = acc[m * 4 + 2 * t];
                const float* cb = acc[m * 4 + 2 * t + 1];
#pragma unroll
                for (int h = 0; h < 2; h++) {
                    const int row = row0 + wm * 32 + m * 16 + gid + h * 8;
                    float xa0 = ca[2 * h] * sa0 + ta0;
                    float xa1 = ca[2 * h + 1] * sa1 + ta1;
                    float xb0 = cb[2 * h] * sb0 + tb0;
                    float xb1 = cb[2 * h + 1] * sb1 + tb1;
                    float o0 = __fdividef(xa0, 1.0f + __expf(-xb0));
                    float o1 = __fdividef(xa1, 1.0f + __expf(-xb1));
                    const size_t ob = (size_t)row * HS + cn;
                    if (resh) {
                        __half2 rh = *(const __half2*)(resh + ob);
                        o0 = fmaf(__half2float(rh.x), 0.70710678118654752f, o0);
                        o1 = fmaf(__half2float(rh.y), 0.70710678118654752f, o1);
                    }
                    __half2 hh;
                    hh.x = __float2half_rn(o0);
                    hh.y = __float2half_rn(o1);
                    *(__half2*)(outh + ob) = hh;
                    if (accp && g < 2) {
                        float2* ap = (float2*)(accp + (size_t)row * OUTD + cn);
                        float2 av = *ap;
                        av.x += fmaxf(o0, 0.0f);
                        av.y += fmaxf(o1, 0.0f);
                        *ap = av;
                    }
                }
            }
        }
    } else {
#pragma unroll
        for (int m = 0; m < 2; m++) {
#pragma unroll
            for (int nb = 0; nb < 4; nb++) {
                const int cn = wn * 32 + nb * 8 + tp * 2;
                const float s0 = sE[cn], s1 = sE[cn + 1];
                const float t0 = tE[cn], t1 = tE[cn + 1];
                const float* ca = acc[m * 4 + nb];
#pragma unroll
                for (int h = 0; h < 2; h++) {
                    const int row = row0 + wm * 32 + m * 16 + gid + h * 8;
                    const size_t idx = (size_t)row * FDIM + g * 128 + cn;
                    float2 zz;
                    zz.x = ca[2 * h] * s0 + t0;
                    zz.y = ca[2 * h + 1] * s1 + t1;
                    if (PR) {
                        float2 pr = *(const float2*)(prior + idx);
                        zz.x *= pr.x;
                        zz.y *= pr.y;
                    }
                    *(float2*)(zout + idx) = zz;
                }
            }
        }

        // ---- last-CTA-out fused sparsemax for this 64-row block ----
        __threadfence();
        __shared__ int s_last;
        __syncthreads();
        if (tid == 0) {
            unsigned old = atomicAdd(&g_cnt[blockIdx.y], 1u);
            int last = (old == 3u);
            s_last = last;
            if (last) g_cnt[blockIdx.y] = 0u;   // reset for next step
        }
        __syncthreads();
        if (!s_last) return;
        __threadfence();   // acquire: z from peer CTAs now ordered

#pragma unroll 1
        for (int rr = 0; rr < 8; rr++) {
            const int grow = row0 + wid * 8 + rr;
            const size_t base = (size_t)grow * 512;
            float v[16];
#pragma unroll
            for (int q = 0; q < 4; q++) {
                float4 t = *(const float4*)(zout + base + q * 128 + lid * 4);
                v[q * 4 + 0] = t.x; v[q * 4 + 1] = t.y;
                v[q * 4 + 2] = t.z; v[q * 4 + 3] = t.w;
            }
            float zmax = v[0];
#pragma unroll
            for (int i = 1; i < 16; i++) zmax = fmaxf(zmax, v[i]);
#pragma unroll
            for (int o = 16; o; o >>= 1)
                zmax = fmaxf(zmax, __shfl_xor_sync(0xffffffffu, zmax, o));

            float lo = zmax - 1.0f, hi = zmax;
            for (int it = 0; it < 20; it++) {
                float mid = 0.5f * (lo + hi);
                float s = 0.0f;
#pragma unroll
                for (int i = 0; i < 16; i++) s += fmaxf(v[i] - mid, 0.0f);
#pragma unroll
                for (int o = 16; o; o >>= 1) s += __shfl_xor_sync(0xffffffffu, s, o);
                if (s >= 1.0f) lo = mid; else hi = mid;
            }
            float sum = 0.0f, cnt = 0.0f;
#pragma unroll
            for (int i = 0; i < 16; i++) {
                if (v[i] > lo) { sum += v[i]; cnt += 1.0f; }
            }
#pragma unroll
            for (int o = 16; o; o >>= 1) {
                sum += __shfl_xor_sync(0xffffffffu, sum, o);
                cnt += __shfl_xor_sync(0xffffffffu, cnt, o);
            }
            const float tau = (sum - 1.0f) / cnt;

#pragma unroll
            for (int q = 0; q < 4; q++) {
                const size_t off = base + q * 128 + lid * 4;
                float4 mk;
                mk.x = fmaxf(v[q * 4 + 0] - tau, 0.0f);
                mk.y = fmaxf(v[q * 4 + 1] - tau, 0.0f);
                mk.z = fmaxf(v[q * 4 + 2] - tau, 0.0f);
                mk.w = fmaxf(v[q * 4 + 3] - tau, 0.0f);
                *(float4*)(maskOut + off) = mk;
                float4 pr;
                if (!PR) {
                    pr.x = 1.5f - mk.x; pr.y = 1.5f - mk.y;
                    pr.z = 1.5f - mk.z; pr.w = 1.5f - mk.w;
                } else {
                    pr = *(const float4*)(prior + off);
                    pr.x *= (1.5f - mk.x); pr.y *= (1.5f - mk.y);
                    pr.z *= (1.5f - mk.z); pr.w *= (1.5f - mk.w);
                }
                *(float4*)(prior + off) = pr;
                __half2 f01 = *(const __half2*)(g_featsh + off);
                __half2 f23 = *(const __half2*)(g_featsh + off + 2);
                __half2 p0, p1;
                p0.x = __float2half_rn(mk.x * __half2float(f01.x));
                p0.y = __float2half_rn(mk.y * __half2float(f01.y));
                p1.x = __float2half_rn(mk.z * __half2float(f23.x));
                p1.y = __float2half_rn(mk.w * __half2float(f23.y));
                *(__half2*)(mf + off) = p0;
                *(__half2*)(mf + off + 2) = p1;
            }
        }
    }
}

// ================= big-tile GEMM for K=512 block-0 ==========================
#define STAGE_B 32768     // A 16K | B 16K
#define PARAM_B (NSTAGE * STAGE_B)
#define SMEM_B  (PARAM_B + 1024)

__global__ __launch_bounds__(256, 2)
void k_mma_b(const fp16* __restrict__ A, int lda, int K,
             const fp16* __restrict__ B,
             const float* __restrict__ bs, const float* __restrict__ bt,
             fp16* __restrict__ outh)
{
    extern __shared__ __align__(128) char smem[];
    const int tid = threadIdx.x, wid = tid >> 5, lid = tid & 31;
    const int wm = wid >> 1, wn = wid & 1;
    const int g = blockIdx.x;
    const int row0 = blockIdx.y * 128;
    const uint32_t sb = smem_u32(smem);

    if (tid < 128) {
        float* sE = (float*)(smem + PARAM_B);
        float* tE = (float*)(smem + PARAM_B + 512);
        int q2 = tid >> 4, rr = tid & 15, half = rr >> 3, jl = rr & 7;
        int col = (half ? 256 : 0) + g * 64 + q2 * 8 + jl;
        sE[tid] = bs[col];
        tE[tid] = bt[col];
    }

    float acc[16][4];
#pragma unroll
    for (int i = 0; i < 16; i++)
#pragma unroll
        for (int j = 0; j < 4; j++) acc[i][j] = 0.0f;

    const int nch = K >> 6;

    const char* gA[4];
    const char* gB[4];
    uint32_t soA[4], soB[4];
#pragma unroll
    for (int i = 0; i < 4; i++) {
        int idx = tid + i * 256;
        int r = idx >> 3, c = idx & 7;
        uint32_t so = (uint32_t)(r * 128 + ((c ^ (r & 7)) << 4));
        soA[i] = so;
        soB[i] = 16384u + so;
        gA[i] = (const char*)(A + (size_t)(row0 + r) * lda + c * 8);
        gB[i] = (const char*)(B + (size_t)(g * 128 + r) * K + c * 8);
    }

    auto load_stage = [&](int ch) {
        const uint32_t st = sb + (ch % NSTAGE) * STAGE_B;
        const int kb = ch << 7;
#pragma unroll
        for (int i = 0; i < 4; i++) {
            cpa16(st + soA[i], gA[i] + kb);
            cpa16(st + soB[i], gB[i] + kb);
        }
    };

#pragma unroll
    for (int p = 0; p < 2; p++) {
        if (p < nch) load_stage(p);
        cpa_commit();
    }

    const int lr = lid & 15, lc = lid >> 4;
    uint32_t offA[2], offB4[4];
#pragma unroll
    for (int m = 0; m < 2; m++) {
        int r = wm * 32 + m * 16 + lr;
        offA[m] = (uint32_t)(r * 128 + ((lc ^ (r & 7)) << 4));
    }
#pragma unroll
    for (int nb = 0; nb < 4; nb++) {
        int r = wn * 64 + nb * 16 + lr;
        offB4[nb] = (uint32_t)(16384 + r * 128 + ((lc ^ (r & 7)) << 4));
    }

    for (int ch = 0; ch < nch; ch++) {
        cpa_wait<1>();
        __syncthreads();
        if (ch + 2 < nch) load_stage(ch + 2);
        cpa_commit();

        const uint32_t st = sb + (ch % NSTAGE) * STAGE_B;
        uint32_t aH0 = st + offA[0], aH1 = st + offA[1];
        uint32_t aB0 = st + offB4[0], aB1 = st + offB4[1];
        uint32_t aB2 = st + offB4[2], aB3 = st + offB4[3];

#pragma unroll
        for (int ks = 0; ks < 4; ks++) {
            uint32_t ah[2][4], bq[4][4];
            ldm4(ah[0], aH0); ldm4(ah[1], aH1);
            ldm4(bq[0], aB0); ldm4(bq[1], aB1);
            ldm4(bq[2], aB2); ldm4(bq[3], aB3);
#pragma unroll
            for (int nb = 0; nb < 4; nb++)
#pragma unroll
                for (int m = 0; m < 2; m++) {
                    mma16(acc[m * 8 + 2 * nb],     ah[m], bq[nb][0], bq[nb][2]);
                    mma16(acc[m * 8 + 2 * nb + 1], ah[m], bq[nb][1], bq[nb][3]);
                }
            const uint32_t d = (ks & 1) ? 96u : 32u;
            aH0 ^= d; aH1 ^= d;
            aB0 ^= d; aB1 ^= d; aB2 ^= d; aB3 ^= d;
        }
    }

    const float* sE = (const float*)(smem + PARAM_B);
    const float* tE = (const float*)(smem + PARAM_B + 512);
    const int gid = lid >> 2, tp = lid & 3;

#pragma unroll
    for (int m = 0; m < 2; m++) {
#pragma unroll
        for (int t = 0; t < 4; t++) {
            const int ja = wn * 64 + t * 16 + tp * 2;
            const int jb = ja + 8;
            const int cn = g * 64 + (wn * 4 + t) * 8 + tp * 2;
            const float sa0 = sE[ja], sa1 = sE[ja + 1];
            const float ta0 = tE[ja], ta1 = tE[ja + 1];
            const float sb0 = sE[jb], sb1 = sE[jb + 1];
            const float tb0 = tE[jb], tb1 = tE[jb + 1];
            const float* ca = acc[m * 8 + 2 * t];
            const float* cb = acc[m * 8 + 2 * t + 1];
#pragma unroll
            for (int h = 0; h < 2; h++) {
                const int row = row0 + wm * 32 + m * 16 + gid + h * 8;
                float xa0 = ca[2 * h] * sa0 + ta0;
                float xa1 = ca[2 * h + 1] * sa1 + ta1;
                float xb0 = cb[2 * h] * sb0 + tb0;
                float xb1 = cb[2 * h + 1] * sb1 + tb1;
                float o0 = __fdividef(xa0, 1.0f + __expf(-xb0));
                float o1 = __fdividef(xa1, 1.0f + __expf(-xb1));
                const size_t ob = (size_t)row * HS + cn;
                __half2 hh;
                hh.x = __float2half_rn(o0);
                hh.y = __float2half_rn(o1);
                *(__half2*)(outh + ob) = hh;
            }
        }
    }
}

// ---------------- final projection ----------------
__global__ __launch_bounds__(256)
void k_fin(const float* __restrict__ A, const float* __restrict__ W,
           const float* __restrict__ bias, float* __restrict__ C)
{
    __shared__ float As[16][128];
    __shared__ float Ws[16][64];
    const int tid = threadIdx.x;
    const int ty = tid >> 4, tx = tid & 15;
    const int row0 = blockIdx.y * 128;
    const int col0 = blockIdx.x * 64;

    float acc[8][4];
#pragma unroll
    for (int r = 0; r < 8; r++)
#pragma unroll
        for (int c = 0; c < 4; c++) acc[r][c] = 0.f;

    for (int kt = 0; kt < 128; kt += 16) {
#pragma unroll
        for (int l = 0; l < 2; l++) {
            int li = tid * 2 + l;
            int r = li >> 2, kq = (li & 3) * 4;
            float4 av = *(const float4*)(A + (size_t)(row0 + r) * 128 + kt + kq);
            As[kq + 0][r] = av.x; As[kq + 1][r] = av.y;
            As[kq + 2][r] = av.z; As[kq + 3][r] = av.w;
        }
        *(float4*)&Ws[tid >> 4][(tid & 15) * 4] =
            *(const float4*)(W + (size_t)(kt + (tid >> 4)) * 128 + col0 + (tid & 15) * 4);
        __syncthreads();
#pragma unroll
        for (int kk = 0; kk < 16; kk++) {
            float a[8];
            float4 a0 = *(float4*)&As[kk][ty * 8];
            float4 a1 = *(float4*)&As[kk][ty * 8 + 4];
            a[0] = a0.x; a[1] = a0.y; a[2] = a0.z; a[3] = a0.w;
            a[4] = a1.x; a[5] = a1.y; a[6] = a1.z; a[7] = a1.w;
            float4 w0 = *(float4*)&Ws[kk][tx * 4];
            float wv[4] = {w0.x, w0.y, w0.z, w0.w};
#pragma unroll
            for (int r = 0; r < 8; r++)
#pragma unroll
                for (int c = 0; c < 4; c++) acc[r][c] += a[r] * wv[c];
        }
        __syncthreads();
    }
#pragma unroll
    for (int r = 0; r < 8; r++) {
        int gr = row0 + ty * 8 + r;
#pragma unroll
        for (int c = 0; c < 4; c++) {
            int gc = col0 + tx * 4 + c;
            C[(size_t)gr * 128 + gc] = acc[r][c] + bias[gc];
        }
    }
}

// ---------------- launch ----------------
extern "C" void kernel_launch(void* const* d_in, const int* in_sizes, int n_in,
                              void* d_out, int out_size)
{
    const float* features = (const float*)d_in[0];
    const float* bn0_g = (const float*)d_in[1];
    const float* bn0_b = (const float*)d_in[2];
    const float* bn0_m = (const float*)d_in[3];
    const float* bn0_v = (const float*)d_in[4];
    const float* Ws0   = (const float*)d_in[5];
    const float* Ws1   = (const float*)d_in[6];
    const float* Wu    = (const float*)d_in[7];
    const float* ft_g  = (const float*)d_in[8];
    const float* ft_b  = (const float*)d_in[9];
    const float* ft_m  = (const float*)d_in[10];
    const float* ft_v  = (const float*)d_in[11];
    const float* W_att = (const float*)d_in[12];
    const float* att_g = (const float*)d_in[13];
    const float* att_b = (const float*)d_in[14];
    const float* att_m = (const float*)d_in[15];
    const float* att_v = (const float*)d_in[16];
    const float* Wf    = (const float*)d_in[17];
    const float* bf    = (const float*)d_in[18];

    float *zp, *prior, *acc;
    fp16 *A, *h0, *h1;
    fp16 *W0, *W1, *WU, *WA;
    float *fts, *ftt, *as, *at;
    cudaGetSymbolAddress((void**)&A, g_A);
    cudaGetSymbolAddress((void**)&h0, g_h0);
    cudaGetSymbolAddress((void**)&h1, g_h1);
    cudaGetSymbolAddress((void**)&zp, g_z);
    cudaGetSymbolAddress((void**)&prior, g_prior);
    cudaGetSymbolAddress((void**)&acc, g_acc);
    cudaGetSymbolAddress((void**)&W0, g_W0);
    cudaGetSymbolAddress((void**)&W1, g_W1);
    cudaGetSymbolAddress((void**)&WU, g_WU);
    cudaGetSymbolAddress((void**)&WA, g_WA);
    cudaGetSymbolAddress((void**)&fts, g_fts);
    cudaGetSymbolAddress((void**)&ftt, g_ftt);
    cudaGetSymbolAddress((void**)&as, g_as);
    cudaGetSymbolAddress((void**)&at, g_at);

    float* outF  = (float*)d_out;
    float* masks = outF + (size_t)BATCH * OUTD;

    static bool attr_set = false;
    if (!attr_set) {
        cudaFuncSetAttribute(k_mma_s<0, 0>, cudaFuncAttributeMaxDynamicSharedMemorySize, SMEM_S);
        cudaFuncSetAttribute(k_mma_s<1, 0>, cudaFuncAttributeMaxDynamicSharedMemorySize, SMEM_S);
        cudaFuncSetAttribute(k_mma_s<1, 1>, cudaFuncAttributeMaxDynamicSharedMemorySize, SMEM_S);
        cudaFuncSetAttribute(k_mma_b, cudaFuncAttributeMaxDynamicSharedMemorySize, SMEM_B);
        attr_set = true;
    }

    k_setup<<<SETUP_BLK, 256>>>(features, bn0_g, bn0_b, bn0_m, bn0_v,
                                Ws0, Ws1, Wu, W_att,
                                ft_g, ft_b, ft_m, ft_v,
                                att_g, att_b, att_m, att_v);

    const dim3 gS(4, BATCH / 64);
    const dim3 gB(4, BATCH / 128);

    auto ft_transformer = [&](int t, float* accOut) {
        const float* s0 = fts + (size_t)t * 4 * 512;
        const float* t0 = ftt + (size_t)t * 4 * 512;
        k_mma_b<<<gB, 256, SMEM_B>>>(A, 512, 512, W0, s0, t0, h0);
        k_mma_s<0, 0><<<gS, 256, SMEM_S>>>(h0, 256, 256, W1,
            s0 + 512, t0 + 512, h0, h1, nullptr, nullptr, nullptr, nullptr, nullptr);
        k_mma_s<0, 0><<<gS, 256, SMEM_S>>>(h1, 256, 256,
            WU + (size_t)(t * 2 + 0) * 512 * 256,
            s0 + 1024, t0 + 1024, h1, h0, nullptr, nullptr, nullptr, nullptr, nullptr);
        k_mma_s<0, 0><<<gS, 256, SMEM_S>>>(h0, 256, 256,
            WU + (size_t)(t * 2 + 1) * 512 * 256,
            s0 + 1536, t0 + 1536, h0, h1, accOut, nullptr, nullptr, nullptr, nullptr);
    };

    ft_transformer(0, nullptr);

    for (int s = 0; s < STEPS; s++) {
        if (s == 0) {
            k_mma_s<1, 0><<<gS, 256, SMEM_S>>>(h1 + 128, 256, 128,
                WA, as, at, nullptr, nullptr, nullptr,
                prior, zp, masks, A);
        } else {
            k_mma_s<1, 1><<<gS, 256, SMEM_S>>>(h1 + 128, 256, 128,
                WA + (size_t)s * 512 * 128,
                as + (size_t)s * 512, at + (size_t)s * 512,
                nullptr, nullptr, nullptr,
                prior, zp, masks + (size_t)s * BATCH * FDIM, A);
        }
        ft_transformer(s + 1, acc);
    }

    k_fin<<<dim3(2, BATCH / 128), 256>>>(acc, Wf, bf, outF);
}